// round 3
// baseline (speedup 1.0000x reference)
#include <cuda_runtime.h>
#include <cuda_bf16.h>

// Problem constants
#define NN 1024
#define HH 16
#define DD 64
#define MM 64
#define NB (NN * HH)          // 16384 independent (n,h) pairs

static constexpr float MU_C  = 0.9f;
static constexpr float EPS_C = 1e-6f;

// Warp-per-(n,h)-pair. No __syncthreads anywhere: each warp is fully
// independent, so the DRAM request stream never stalls on inter-warp barriers.
// Lane l: m-group g = l & 15 (4 consecutive m), row-half hl = l >> 4.
// Iteration it processes rows d = 2*it + hl  -> warp covers 512 contiguous B
// per load/store (2 rows x 64 floats).
__global__ __launch_bounds__(256, 5)
void rma_kernel(const float* __restrict__ q_in,
                const float* __restrict__ k_in,
                const float* __restrict__ v_in,
                const float* __restrict__ Si_in,
                const float* __restrict__ Zi_in,
                const float* __restrict__ Pi_in,
                float* __restrict__ Vout,
                float* __restrict__ Sout,
                float* __restrict__ Zout,
                float* __restrict__ Pout)
{
    const int wid = threadIdx.x >> 5;   // warp in CTA (0..7)
    const int l   = threadIdx.x & 31;   // lane
    const int b   = blockIdx.x * 8 + wid;   // (n*H + h), grid=2048 -> exact cover

    __shared__ float sQ[8][DD];
    __shared__ float sK[8][DD];

    const int base64   = b * 64;
    const int base4096 = b * 4096;

    // ---- small vectors: 2 elements per lane ----
    const float2 q2 = ((const float2*)(q_in  + base64))[l];
    const float2 k2 = ((const float2*)(k_in  + base64))[l];
    const float2 z2 = ((const float2*)(Zi_in + base64))[l];
    const float2 v2 = ((const float2*)(v_in  + base64))[l];

    float2 fq, fk;
    fq.x = (q2.x > 0.f) ? (q2.x + 1.f) : __expf(q2.x);   // elu(x)+1
    fq.y = (q2.y > 0.f) ? (q2.y + 1.f) : __expf(q2.y);
    fk.x = (k2.x > 0.f) ? (k2.x + 1.f) : __expf(k2.x);
    fk.y = (k2.y > 0.f) ? (k2.y + 1.f) : __expf(k2.y);

    float2 zn;
    zn.x = z2.x + fk.x;
    zn.y = z2.y + fk.y;
    ((float2*)(Zout + base64))[l] = zn;

    // stage fq/fk in this warp's private smem slice
    ((float2*)(&sQ[wid][0]))[l] = fq;
    ((float2*)(&sK[wid][0]))[l] = fk;

    // warp-reduce Q . Zi_new (butterfly -> all lanes hold the sum)
    float dot = fq.x * zn.x + fq.y * zn.y;
    #pragma unroll
    for (int off = 16; off > 0; off >>= 1)
        dot += __shfl_xor_sync(0xffffffffu, dot, off);
    const float Zs = 1.0f / (dot + EPS_C);

    // gather val4 (m = 4g..4g+3) from lane-distributed v2 via shuffles
    const int g  = l & 15;
    const int hl = l >> 4;
    float4 val4;
    val4.x = __shfl_sync(0xffffffffu, v2.x, 2 * g);
    val4.y = __shfl_sync(0xffffffffu, v2.y, 2 * g);
    val4.z = __shfl_sync(0xffffffffu, v2.x, 2 * g + 1);
    val4.w = __shfl_sync(0xffffffffu, v2.y, 2 * g + 1);

    __syncwarp();   // smem fq/fk visible within warp

    const float4* __restrict__ Pi4 = (const float4*)(Pi_in + base4096);
    const float4* __restrict__ Si4 = (const float4*)(Si_in + base4096);
    float4* __restrict__ Po4 = (float4*)(Pout + base4096);
    float4* __restrict__ So4 = (float4*)(Sout + base4096);

    float4 vacc = make_float4(0.f, 0.f, 0.f, 0.f);

    #pragma unroll 4
    for (int it = 0; it < 32; ++it) {
        const int d   = 2 * it + hl;
        const int off = d * 16 + g;

        const float4 p = __ldcs(Pi4 + off);
        const float4 s = __ldcs(Si4 + off);
        const float kk = sK[wid][d];
        const float qq = sQ[wid][d];

        float4 pn, sn;
        pn.x = MU_C * p.x - kk * val4.x;
        pn.y = MU_C * p.y - kk * val4.y;
        pn.z = MU_C * p.z - kk * val4.z;
        pn.w = MU_C * p.w - kk * val4.w;

        sn.x = s.x - pn.x;
        sn.y = s.y - pn.y;
        sn.z = s.z - pn.z;
        sn.w = s.w - pn.w;

        __stcs(Po4 + off, pn);
        __stcs(So4 + off, sn);

        vacc.x += qq * sn.x;
        vacc.y += qq * sn.y;
        vacc.z += qq * sn.z;
        vacc.w += qq * sn.w;
    }

    // combine the two row-halves, scale by Z, store V (lanes 0..15)
    vacc.x += __shfl_xor_sync(0xffffffffu, vacc.x, 16);
    vacc.y += __shfl_xor_sync(0xffffffffu, vacc.y, 16);
    vacc.z += __shfl_xor_sync(0xffffffffu, vacc.z, 16);
    vacc.w += __shfl_xor_sync(0xffffffffu, vacc.w, 16);

    if (hl == 0) {
        float4 o;
        o.x = vacc.x * Zs;
        o.y = vacc.y * Zs;
        o.z = vacc.z * Zs;
        o.w = vacc.w * Zs;
        ((float4*)(Vout + base64))[g] = o;
    }
}

extern "C" void kernel_launch(void* const* d_in, const int* in_sizes, int n_in,
                              void* d_out, int out_size) {
    // metadata order: query, key, value, Si, Zi, Pi
    const float* q  = (const float*)d_in[0];
    const float* k  = (const float*)d_in[1];
    const float* v  = (const float*)d_in[2];
    const float* Si = (const float*)d_in[3];
    const float* Zi = (const float*)d_in[4];
    const float* Pi = (const float*)d_in[5];

    float* out = (float*)d_out;
    // reference returns (V, Si_new, Zi_new, Pi_new) -> concatenated flat
    float* Vout = out;
    float* Sout = Vout + (size_t)NN * HH * MM;
    float* Zout = Sout + (size_t)NN * HH * DD * MM;
    float* Pout = Zout + (size_t)NN * HH * DD;

    rma_kernel<<<NB / 8, 256>>>(q, k, v, Si, Zi, Pi, Vout, Sout, Zout, Pout);
}

// round 4
// speedup vs baseline: 1.0600x; 1.0600x over previous
#include <cuda_runtime.h>
#include <cuda_bf16.h>

#define NN 1024
#define HH 16
#define DD 64
#define MM 64
#define NB (NN * HH)          // 16384 independent (n,h) pairs

static constexpr float MU_C  = 0.9f;
static constexpr float EPS_C = 1e-6f;

__device__ __forceinline__ float elu1(float x) {
    return (x > 0.f) ? (x + 1.f) : __expf(x);
}

// 2 pairs per CTA, 256 threads. Pair0's 8 float4 loads are front-batched at
// entry; pair1's 8 loads are issued right after pair0's registers die, so the
// pair0 epilogue (the only load-free window in the R2 kernel) runs with a full
// load batch in flight. Small-vector work for both pairs is done by disjoint
// warp groups up front.
__global__ __launch_bounds__(256, 4)
void rma_kernel(const float* __restrict__ q_in,
                const float* __restrict__ k_in,
                const float* __restrict__ v_in,
                const float* __restrict__ Si_in,
                const float* __restrict__ Zi_in,
                const float* __restrict__ Pi_in,
                float* __restrict__ Vout,
                float* __restrict__ Sout,
                float* __restrict__ Zout,
                float* __restrict__ Pout)
{
    const int t  = threadIdx.x;
    const int b0 = blockIdx.x * 2;
    const int b1 = b0 + 1;

    __shared__ float  sQ[2][DD];
    __shared__ float  sK[2][DD];
    __shared__ float  sVal[2][MM];
    __shared__ float  sDot[2][2];
    __shared__ float  sZ[2];
    __shared__ float4 sAcc[2][256];

    const int base64_0   = b0 * 64;
    const int base64_1   = b1 * 64;
    const int base4096_0 = b0 * 4096;
    const int base4096_1 = b1 * 4096;

    const int g    = t & 15;            // float4 column group (m = 4g..4g+3)
    const int drow = t >> 4;            // 0..15

    const int o0 = (drow +  0) * 16 + g;
    const int o1 = (drow + 16) * 16 + g;
    const int o2 = (drow + 32) * 16 + g;
    const int o3 = (drow + 48) * 16 + g;

    const float4* __restrict__ Pi4_0 = (const float4*)(Pi_in + base4096_0);
    const float4* __restrict__ Si4_0 = (const float4*)(Si_in + base4096_0);
    const float4* __restrict__ Pi4_1 = (const float4*)(Pi_in + base4096_1);
    const float4* __restrict__ Si4_1 = (const float4*)(Si_in + base4096_1);
    float4* __restrict__ Po4_0 = (float4*)(Pout + base4096_0);
    float4* __restrict__ So4_0 = (float4*)(Sout + base4096_0);
    float4* __restrict__ Po4_1 = (float4*)(Pout + base4096_1);
    float4* __restrict__ So4_1 = (float4*)(Sout + base4096_1);

    // ---- pair0 big loads: front-batched, evict-first ----
    float4 p0 = __ldcs(Pi4_0 + o0);
    float4 p1 = __ldcs(Pi4_0 + o1);
    float4 p2 = __ldcs(Pi4_0 + o2);
    float4 p3 = __ldcs(Pi4_0 + o3);
    float4 s0 = __ldcs(Si4_0 + o0);
    float4 s1 = __ldcs(Si4_0 + o1);
    float4 s2 = __ldcs(Si4_0 + o2);
    float4 s3 = __ldcs(Si4_0 + o3);

    // ---- small vectors for BOTH pairs, disjoint warp groups (overlaps loads) ----
    if (t < 128) {
        const int pr   = t >> 6;                        // 0 or 1
        const int e    = t & 63;                        // element 0..63
        const int base = pr ? base64_1 : base64_0;

        float fq = elu1(q_in[base + e]);
        float fk = elu1(k_in[base + e]);
        sQ[pr][e] = fq;
        sK[pr][e] = fk;

        float zn = Zi_in[base + e] + fk;
        Zout[base + e] = zn;

        float d = fq * zn;
        #pragma unroll
        for (int off = 16; off > 0; off >>= 1)
            d += __shfl_down_sync(0xffffffffu, d, off);
        if ((t & 31) == 0) sDot[pr][(e >> 5) & 1] = d;
    } else {
        const int pr   = (t >> 6) & 1;                  // t 128..191 -> 0, 192..255 -> 1
        const int m    = t & 63;
        const int base = pr ? base64_1 : base64_0;
        sVal[pr][m] = v_in[base + m];
    }
    __syncthreads();

    if (t < 2) sZ[t] = 1.0f / (sDot[t][0] + sDot[t][1] + EPS_C);
    // sZ[0] read after barrier2, sZ[1] after barrier3

    #define DO_ROW(pp, ss, kk, qq, Po, So, oo, vacc)                 \
    {                                                                \
        float4 pn, sn;                                               \
        pn.x = MU_C * (pp).x - (kk) * val4.x;                        \
        pn.y = MU_C * (pp).y - (kk) * val4.y;                        \
        pn.z = MU_C * (pp).z - (kk) * val4.z;                        \
        pn.w = MU_C * (pp).w - (kk) * val4.w;                        \
        sn.x = (ss).x - pn.x;                                        \
        sn.y = (ss).y - pn.y;                                        \
        sn.z = (ss).z - pn.z;                                        \
        sn.w = (ss).w - pn.w;                                        \
        __stcs(Po + (oo), pn);                                       \
        __stcs(So + (oo), sn);                                       \
        vacc.x += (qq) * sn.x;                                       \
        vacc.y += (qq) * sn.y;                                       \
        vacc.z += (qq) * sn.z;                                       \
        vacc.w += (qq) * sn.w;                                       \
    }

    // ---- pair0 compute + stores ----
    {
        const float4 val4 = ((const float4*)sVal[0])[g];
        const float kk0 = sK[0][drow +  0], qq0 = sQ[0][drow +  0];
        const float kk1 = sK[0][drow + 16], qq1 = sQ[0][drow + 16];
        const float kk2 = sK[0][drow + 32], qq2 = sQ[0][drow + 32];
        const float kk3 = sK[0][drow + 48], qq3 = sQ[0][drow + 48];

        float4 vacc = make_float4(0.f, 0.f, 0.f, 0.f);
        DO_ROW(p0, s0, kk0, qq0, Po4_0, So4_0, o0, vacc)
        DO_ROW(p1, s1, kk1, qq1, Po4_0, So4_0, o1, vacc)
        DO_ROW(p2, s2, kk2, qq2, Po4_0, So4_0, o2, vacc)
        DO_ROW(p3, s3, kk3, qq3, Po4_0, So4_0, o3, vacc)
        sAcc[0][t] = vacc;
    }

    // ---- pair1 big loads: in flight across the pair0 epilogue ----
    p0 = __ldcs(Pi4_1 + o0);
    p1 = __ldcs(Pi4_1 + o1);
    p2 = __ldcs(Pi4_1 + o2);
    p3 = __ldcs(Pi4_1 + o3);
    s0 = __ldcs(Si4_1 + o0);
    s1 = __ldcs(Si4_1 + o1);
    s2 = __ldcs(Si4_1 + o2);
    s3 = __ldcs(Si4_1 + o3);

    __syncthreads();

    // ---- pair0 V readout ----
    if (t < MM) {
        const int gg = t >> 2;
        const int c  = t & 3;
        const float* accf = (const float*)sAcc[0];
        float sum = 0.f;
        #pragma unroll
        for (int r = 0; r < 16; ++r)
            sum += accf[(r * 16 + gg) * 4 + c];
        Vout[base64_0 + t] = sum * sZ[0];
    }

    // ---- pair1 compute + stores ----
    {
        const float4 val4 = ((const float4*)sVal[1])[g];
        const float kk0 = sK[1][drow +  0], qq0 = sQ[1][drow +  0];
        const float kk1 = sK[1][drow + 16], qq1 = sQ[1][drow + 16];
        const float kk2 = sK[1][drow + 32], qq2 = sQ[1][drow + 32];
        const float kk3 = sK[1][drow + 48], qq3 = sQ[1][drow + 48];

        float4 vacc = make_float4(0.f, 0.f, 0.f, 0.f);
        DO_ROW(p0, s0, kk0, qq0, Po4_1, So4_1, o0, vacc)
        DO_ROW(p1, s1, kk1, qq1, Po4_1, So4_1, o1, vacc)
        DO_ROW(p2, s2, kk2, qq2, Po4_1, So4_1, o2, vacc)
        DO_ROW(p3, s3, kk3, qq3, Po4_1, So4_1, o3, vacc)
        sAcc[1][t] = vacc;
    }
    #undef DO_ROW

    __syncthreads();

    // ---- pair1 V readout ----
    if (t < MM) {
        const int gg = t >> 2;
        const int c  = t & 3;
        const float* accf = (const float*)sAcc[1];
        float sum = 0.f;
        #pragma unroll
        for (int r = 0; r < 16; ++r)
            sum += accf[(r * 16 + gg) * 4 + c];
        Vout[base64_1 + t] = sum * sZ[1];
    }
}

extern "C" void kernel_launch(void* const* d_in, const int* in_sizes, int n_in,
                              void* d_out, int out_size) {
    // metadata order: query, key, value, Si, Zi, Pi
    const float* q  = (const float*)d_in[0];
    const float* k  = (const float*)d_in[1];
    const float* v  = (const float*)d_in[2];
    const float* Si = (const float*)d_in[3];
    const float* Zi = (const float*)d_in[4];
    const float* Pi = (const float*)d_in[5];

    float* out = (float*)d_out;
    // reference returns (V, Si_new, Zi_new, Pi_new) -> concatenated flat
    float* Vout = out;
    float* Sout = Vout + (size_t)NN * HH * MM;
    float* Zout = Sout + (size_t)NN * HH * DD * MM;
    float* Pout = Zout + (size_t)NN * HH * DD;

    rma_kernel<<<NB / 2, 256>>>(q, k, v, Si, Zi, Pi, Vout, Sout, Zout, Pout);
}

// round 5
// speedup vs baseline: 1.0654x; 1.0051x over previous
#include <cuda_runtime.h>
#include <cuda_bf16.h>

#define NN 1024
#define HH 16
#define DD 64
#define MM 64
#define NB (NN * HH)          // 16384 independent (n,h) pairs

static constexpr float MU_C  = 0.9f;
static constexpr float EPS_C = 1e-6f;

__device__ __forceinline__ float elu1(float x) {
    return (x > 0.f) ? (x + 1.f) : __expf(x);
}

// One CTA per (n,h), 256 threads, ONE barrier total.
// - 8 big float4 loads hoisted to entry (front-batched MLP=8).
// - kk/qq/val4 computed redundantly per thread from L1-broadcast 256B regions,
//   so the main stream needs NO pre-barrier: every warp flows independently.
// - Warps 0-1 additionally produce Zi_new / dot partials (sDot); the single
//   __syncthreads() before the V readout orders those and sAcc.
__global__ __launch_bounds__(256, 5)
void rma_kernel(const float* __restrict__ q_in,
                const float* __restrict__ k_in,
                const float* __restrict__ v_in,
                const float* __restrict__ Si_in,
                const float* __restrict__ Zi_in,
                const float* __restrict__ Pi_in,
                float* __restrict__ Vout,
                float* __restrict__ Sout,
                float* __restrict__ Zout,
                float* __restrict__ Pout)
{
    const int b = blockIdx.x;
    const int t = threadIdx.x;

    __shared__ float  sDot[2];
    __shared__ float4 sAcc[256];

    const int base64   = b * 64;
    const int base4096 = b * 4096;

    const int g    = t & 15;            // float4 column group (m = 4g..4g+3)
    const int drow = t >> 4;            // 0..15

    const int o0 = (drow +  0) * 16 + g;
    const int o1 = (drow + 16) * 16 + g;
    const int o2 = (drow + 32) * 16 + g;
    const int o3 = (drow + 48) * 16 + g;

    const float4* __restrict__ Pi4 = (const float4*)(Pi_in + base4096);
    const float4* __restrict__ Si4 = (const float4*)(Si_in + base4096);

    // ---- front-batched big loads (evict-first) ----
    float4 p0 = __ldcs(Pi4 + o0);
    float4 p1 = __ldcs(Pi4 + o1);
    float4 p2 = __ldcs(Pi4 + o2);
    float4 p3 = __ldcs(Pi4 + o3);
    float4 s0 = __ldcs(Si4 + o0);
    float4 s1 = __ldcs(Si4 + o1);
    float4 s2 = __ldcs(Si4 + o2);
    float4 s3 = __ldcs(Si4 + o3);

    // ---- redundant per-thread small loads (L1-broadcast, overlap big-load latency) ----
    const float4 v4  = __ldg((const float4*)(v_in + base64) + g);
    const float  k0r = __ldg(k_in + base64 + drow +  0);
    const float  k1r = __ldg(k_in + base64 + drow + 16);
    const float  k2r = __ldg(k_in + base64 + drow + 32);
    const float  k3r = __ldg(k_in + base64 + drow + 48);
    const float  q0r = __ldg(q_in + base64 + drow +  0);
    const float  q1r = __ldg(q_in + base64 + drow + 16);
    const float  q2r = __ldg(q_in + base64 + drow + 32);
    const float  q3r = __ldg(q_in + base64 + drow + 48);

    // ---- warps 0-1: Zi update + dot partials (no other warp depends on this
    //      until the single barrier below) ----
    if (t < DD) {
        float fq = elu1(q_in[base64 + t]);
        float fk = elu1(k_in[base64 + t]);
        float zn = Zi_in[base64 + t] + fk;
        Zout[base64 + t] = zn;

        float d = fq * zn;
        #pragma unroll
        for (int off = 16; off > 0; off >>= 1)
            d += __shfl_down_sync(0xffffffffu, d, off);
        if ((t & 31) == 0) sDot[t >> 5] = d;
    }

    const float kk0 = elu1(k0r), qq0 = elu1(q0r);
    const float kk1 = elu1(k1r), qq1 = elu1(q1r);
    const float kk2 = elu1(k2r), qq2 = elu1(q2r);
    const float kk3 = elu1(k3r), qq3 = elu1(q3r);

    float4* __restrict__ Po4 = (float4*)(Pout + base4096);
    float4* __restrict__ So4 = (float4*)(Sout + base4096);

    float4 vacc = make_float4(0.f, 0.f, 0.f, 0.f);

    #define DO_ROW(pp, ss, kk, qq, oo)                              \
    {                                                               \
        float4 pn, sn;                                              \
        pn.x = MU_C * (pp).x - (kk) * v4.x;                         \
        pn.y = MU_C * (pp).y - (kk) * v4.y;                         \
        pn.z = MU_C * (pp).z - (kk) * v4.z;                         \
        pn.w = MU_C * (pp).w - (kk) * v4.w;                         \
        sn.x = (ss).x - pn.x;                                       \
        sn.y = (ss).y - pn.y;                                       \
        sn.z = (ss).z - pn.z;                                       \
        sn.w = (ss).w - pn.w;                                       \
        __stcs(Po4 + (oo), pn);                                     \
        __stcs(So4 + (oo), sn);                                     \
        vacc.x += (qq) * sn.x;                                      \
        vacc.y += (qq) * sn.y;                                      \
        vacc.z += (qq) * sn.z;                                      \
        vacc.w += (qq) * sn.w;                                      \
    }

    DO_ROW(p0, s0, kk0, qq0, o0)
    DO_ROW(p1, s1, kk1, qq1, o1)
    DO_ROW(p2, s2, kk2, qq2, o2)
    DO_ROW(p3, s3, kk3, qq3, o3)
    #undef DO_ROW

    sAcc[t] = vacc;
    __syncthreads();          // the ONLY barrier: orders sAcc + sDot

    // ---- V readout: reduce 16 row-partials per m, scale by Z ----
    if (t < MM) {
        const float Zs = 1.0f / (sDot[0] + sDot[1] + EPS_C);
        const int gg = t >> 2;
        const int c  = t & 3;
        const float* accf = (const float*)sAcc;
        float sum = 0.f;
        #pragma unroll
        for (int r = 0; r < 16; ++r)
            sum += accf[(r * 16 + gg) * 4 + c];
        Vout[base64 + t] = sum * Zs;
    }
}

extern "C" void kernel_launch(void* const* d_in, const int* in_sizes, int n_in,
                              void* d_out, int out_size) {
    // metadata order: query, key, value, Si, Zi, Pi
    const float* q  = (const float*)d_in[0];
    const float* k  = (const float*)d_in[1];
    const float* v  = (const float*)d_in[2];
    const float* Si = (const float*)d_in[3];
    const float* Zi = (const float*)d_in[4];
    const float* Pi = (const float*)d_in[5];

    float* out = (float*)d_out;
    // reference returns (V, Si_new, Zi_new, Pi_new) -> concatenated flat
    float* Vout = out;
    float* Sout = Vout + (size_t)NN * HH * MM;
    float* Zout = Sout + (size_t)NN * HH * DD * MM;
    float* Pout = Zout + (size_t)NN * HH * DD;

    rma_kernel<<<NB, 256>>>(q, k, v, Si, Zi, Pi, Vout, Sout, Zout, Pout);
}